// round 15
// baseline (speedup 1.0000x reference)
#include <cuda_runtime.h>
#include <cstdint>
#include <cstring>

#define PPTS   32
#define C_OUT  64
#define BN_EPS 1e-3f
#define MAXN   100000

#define NBLK1   592              // 148 SM * 4 resident blocks
#define THREADS1 256
#define WARPS1   8

__device__ float g_max[MAXN * C_OUT];
__device__ float g_partial[NBLK1 * 2 * C_OUT];
__device__ float g_scale[C_OUT];
__device__ float g_shift[C_OUT];

// ---- packed f32x2 helpers (Blackwell) -------------------------------------
typedef unsigned long long ull;
__device__ __forceinline__ ull pk2(float lo, float hi) {
    ull r; asm("mov.b64 %0, {%1, %2};" : "=l"(r) : "f"(lo), "f"(hi)); return r;
}
__device__ __forceinline__ ull fma2(ull a, ull b, ull c) {
    ull d; asm("fma.rn.f32x2 %0, %1, %2, %3;" : "=l"(d) : "l"(a), "l"(b), "l"(c)); return d;
}
__device__ __forceinline__ ull mul2(ull a, ull b) {
    ull d; asm("mul.rn.f32x2 %0, %1, %2;" : "=l"(d) : "l"(a), "l"(b)); return d;
}
__device__ __forceinline__ ull add2(ull a, ull b) {
    ull d; asm("add.rn.f32x2 %0, %1, %2;" : "=l"(d) : "l"(a), "l"(b)); return d;
}
// zero-cost reinterpret: lets the register allocator alias the packed pair
__device__ __forceinline__ float2 u2f(ull x) {
    float2 f; memcpy(&f, &x, 8); return f;
}

// ---------------------------------------------------------------------------
// Pass 1: warp = pillar. SoA smem tile; f32x2 packs two POINTS (same channel).
// Each thread owns channels (lane, lane+32). Quad loop: 4 points/iter via
// one LDS.128 per component; scalar remainder for np & 3.
// The STS->LDS ordering inside an iteration is enforced by the warp-
// synchronizing shfl.sync chain; only a compiler fence is needed there.
// ---------------------------------------------------------------------------
__global__ __launch_bounds__(THREADS1, 4) void pfn_pass1(
    const float4* __restrict__ voxels,    // [N,32] float4
    const int*    __restrict__ npts_arr,  // [N]
    const float2* __restrict__ centers,   // [N]
    const float*  __restrict__ W,         // [64,9]
    int N)
{
    const int tid  = threadIdx.x;
    const int lane = tid & 31;
    const int wrp  = tid >> 5;
    const int oA = lane, oB = lane + 32;

    const float* wa = W + oA * 9;
    const float* wb = W + oB * 9;
    // folded weights, per channel (scalar)
    const float a0 = wa[0] + wa[4] + wa[7], b0 = wb[0] + wb[4] + wb[7];
    const float a1 = wa[1] + wa[5] + wa[8], b1 = wb[1] + wb[5] + wb[8];
    const float a2 = wa[2] + wa[6],         b2 = wb[2] + wb[6];
    const float a3 = wa[3],                 b3 = wb[3];
    // point-parity-packed duplicates for the quad loop
    const ull A0 = pk2(a0, a0), A1 = pk2(a1, a1), A2 = pk2(a2, a2), A3 = pk2(a3, a3);
    const ull B0 = pk2(b0, b0), B1 = pk2(b1, b1), B2 = pk2(b2, b2), B3 = pk2(b3, b3);
    const float w4a = wa[4], w5a = wa[5], w6a = wa[6], w7a = wa[7], w8a = wa[8];
    const float w4b = wb[4], w5b = wb[5], w6b = wb[6], w7b = wb[7], w8b = wb[8];

    // SoA: per warp, components contiguous: x[32] y[32] z[32] w[32]
    __shared__ float vox_soa[WARPS1][4][PPTS];

    ull sp  = 0ull;   // packed (sumA, sumB) with bias folded
    ull s2p = 0ull;   // packed (sumsqA, sumsqB)

    const int stride = gridDim.x * WARPS1;
    int n = blockIdx.x * WARPS1 + wrp;

    float4 v = make_float4(0.f, 0.f, 0.f, 0.f);
    int np = 1;
    float2 c = make_float2(0.f, 0.f);
    if (n < N) {
        v  = voxels[(size_t)n * PPTS + lane];
        np = npts_arr[n];
        c  = centers[n];
    }

    while (n < N) {
        // SoA staging: 4 conflict-free STS.32
        vox_soa[wrp][0][lane] = v.x;
        vox_soa[wrp][1][lane] = v.y;
        vox_soa[wrp][2][lane] = v.z;
        vox_soa[wrp][3][lane] = v.w;
        asm volatile("" ::: "memory");   // compiler fence; shfl chain below
                                         // provides the execution sync

        // mean shuffles (reference sums ALL 32 rows, divides by np)
        float sx = v.x, sy = v.y, sz = v.z;
        #pragma unroll
        for (int off = 16; off > 0; off >>= 1) {
            sx += __shfl_xor_sync(0xffffffffu, sx, off);
            sy += __shfl_xor_sync(0xffffffffu, sy, off);
            sz += __shfl_xor_sync(0xffffffffu, sz, off);
        }

        // prefetch next pillar
        const int n2 = n + stride;
        float4 v2 = v; int np2 = np; float2 c2 = c;
        if (n2 < N) {
            v2  = voxels[(size_t)n2 * PPTS + lane];
            np2 = npts_arr[n2];
            c2  = centers[n2];
        }

        // ---- quad loop: 4 points per iteration -------------------------
        float mA = -3.402823466e38f, mB = -3.402823466e38f;
        ull sA = 0ull, sB = 0ull;        // point-parity packed sums per channel
        ull qA = 0ull, qB = 0ull;        // packed sumsq per channel

        const char* base = (const char*)&vox_soa[wrp][0][0];
        const int nq = np >> 2;
        #pragma unroll 2
        for (int q = 0; q < nq; q++) {
            const ulonglong2 xq = *(const ulonglong2*)(base + q * 16);
            const ulonglong2 yq = *(const ulonglong2*)(base + 128 + q * 16);
            const ulonglong2 zq = *(const ulonglong2*)(base + 256 + q * 16);
            const ulonglong2 wq = *(const ulonglong2*)(base + 384 + q * 16);

            const ull yA01 = fma2(A0, xq.x, fma2(A1, yq.x, fma2(A2, zq.x, mul2(A3, wq.x))));
            const ull yA23 = fma2(A0, xq.y, fma2(A1, yq.y, fma2(A2, zq.y, mul2(A3, wq.y))));
            const ull yB01 = fma2(B0, xq.x, fma2(B1, yq.x, fma2(B2, zq.x, mul2(B3, wq.x))));
            const ull yB23 = fma2(B0, xq.y, fma2(B1, yq.y, fma2(B2, zq.y, mul2(B3, wq.y))));

            const float2 a01 = u2f(yA01), a23 = u2f(yA23);
            mA = fmaxf(fmaxf(mA, fmaxf(a01.x, a01.y)), fmaxf(a23.x, a23.y));
            const float2 b01 = u2f(yB01), b23 = u2f(yB23);
            mB = fmaxf(fmaxf(mB, fmaxf(b01.x, b01.y)), fmaxf(b23.x, b23.y));

            sA = add2(sA, add2(yA01, yA23));
            sB = add2(sB, add2(yB01, yB23));
            qA = fma2(yA01, yA01, fma2(yA23, yA23, qA));
            qB = fma2(yB01, yB01, fma2(yB23, yB23, qB));
        }

        // ---- scalar remainder (np & 3 points) ---------------------------
        float sAr = 0.f, sBr = 0.f, qAr = 0.f, qBr = 0.f;
        for (int p = nq << 2; p < np; p++) {
            const float xx = vox_soa[wrp][0][p];
            const float yy = vox_soa[wrp][1][p];
            const float zz = vox_soa[wrp][2][p];
            const float ww = vox_soa[wrp][3][p];
            const float yA = fmaf(a0, xx, fmaf(a1, yy, fmaf(a2, zz, a3 * ww)));
            const float yB = fmaf(b0, xx, fmaf(b1, yy, fmaf(b2, zz, b3 * ww)));
            mA = fmaxf(mA, yA);
            mB = fmaxf(mB, yB);
            sAr += yA; sBr += yB;
            qAr = fmaf(yA, yA, qAr);
            qBr = fmaf(yB, yB, qBr);
        }

        // ---- epilogue: fold bias into max / sum / sumsq -----------------
        const float rnp = 1.0f / (float)np;
        const float m0 = sx * rnp, m1 = sy * rnp, m2 = sz * rnp;
        const float bA = -(w4a * m0 + w5a * m1 + w6a * m2 + w7a * c.x + w8a * c.y);
        const float bB = -(w4b * m0 + w5b * m1 + w6b * m2 + w7b * c.x + w8b * c.y);

        float fA = mA + bA, fB = mB + bB;
        if (np < PPTS) {                 // padded points contribute exactly 0
            fA = fmaxf(fA, 0.0f);
            fB = fmaxf(fB, 0.0f);
        }
        g_max[(size_t)n * C_OUT + oA] = fA;
        g_max[(size_t)n * C_OUT + oB] = fB;

        const float2 sAf = u2f(sA), qAf = u2f(qA);
        const float2 sBf = u2f(sB), qBf = u2f(qB);
        const float SyA = sAf.x + sAf.y + sAr;   // Σy, channel A
        const float QyA = qAf.x + qAf.y + qAr;   // Σy²
        const float SyB = sBf.x + sBf.y + sBr;
        const float QyB = qBf.x + qBf.y + qBr;

        const float npf = (float)np;
        // Σ(y+b) = Σy + np·b ;  Σ(y+b)² = Σy² + b(2Σy + np·b)
        const ull Sy2 = pk2(SyA, SyB);
        const ull Qy2 = pk2(QyA, QyB);
        const ull bp  = pk2(bA, bB);
        const ull npf2 = pk2(npf, npf);
        sp  = add2(sp, fma2(npf2, bp, Sy2));
        s2p = add2(s2p, fma2(bp, fma2(npf2, bp, add2(Sy2, Sy2)), Qy2));

        __syncwarp();    // all lanes done reading smem before next staging
        v = v2; np = np2; c = c2; n = n2;
    }

    // deterministic block reduction across warps
    __shared__ float rsm[WARPS1][C_OUT];
    __shared__ float rqm[WARPS1][C_OUT];
    const float2 spf = u2f(sp), s2f = u2f(s2p);
    rsm[wrp][oA] = spf.x; rsm[wrp][oB] = spf.y;
    rqm[wrp][oA] = s2f.x; rqm[wrp][oB] = s2f.y;
    __syncthreads();
    if (tid < C_OUT) {
        float ts = 0.0f, tq = 0.0f;
        #pragma unroll
        for (int g = 0; g < WARPS1; g++) { ts += rsm[g][tid]; tq += rqm[g][tid]; }
        g_partial[blockIdx.x * 2 * C_OUT + tid]         = ts;
        g_partial[blockIdx.x * 2 * C_OUT + C_OUT + tid] = tq;
    }
}

// ---------------------------------------------------------------------------
// Pass 2: 64 blocks, one per channel. Deterministic fixed-order reduction.
// ---------------------------------------------------------------------------
#define P2_THREADS 128
__global__ __launch_bounds__(P2_THREADS) void pfn_pass2(
    const float* __restrict__ gamma, const float* __restrict__ beta, int N)
{
    const int o = blockIdx.x;           // channel
    const int t = threadIdx.x;

    float s = 0.0f, q = 0.0f;
    for (int b = t; b < NBLK1; b += P2_THREADS) {   // fixed order per thread
        s += g_partial[b * 2 * C_OUT + o];
        q += g_partial[b * 2 * C_OUT + C_OUT + o];
    }
    __shared__ float ss[P2_THREADS], qq[P2_THREADS];
    ss[t] = s; qq[t] = q;
    __syncthreads();
    #pragma unroll
    for (int w = P2_THREADS / 2; w > 0; w >>= 1) {   // deterministic tree
        if (t < w) { ss[t] += ss[t + w]; qq[t] += qq[t + w]; }
        __syncthreads();
    }
    if (t == 0) {
        const float inv  = 1.0f / ((float)N * (float)PPTS);
        const float mean = ss[0] * inv;
        const float var  = fmaf(-mean, mean, qq[0] * inv);
        const float sc   = gamma[o] * rsqrtf(var + BN_EPS);
        g_scale[o] = sc;
        g_shift[o] = fmaf(-sc, mean, beta[o]);
    }
}

// ---------------------------------------------------------------------------
// Pass 3: out = relu(scale * g_max + shift)   (scale > 0 since gamma == 1,
// so the affine+relu commutes with the max computed in pass 1)
// Exact grid: one float4 per thread, no loop.
// ---------------------------------------------------------------------------
__global__ __launch_bounds__(256) void pfn_pass3(float* __restrict__ out, int N)
{
    __shared__ float sc_s[C_OUT], sh_s[C_OUT];
    if (threadIdx.x < C_OUT) {
        sc_s[threadIdx.x] = g_scale[threadIdx.x];
        sh_s[threadIdx.x] = g_shift[threadIdx.x];
    }
    __syncthreads();
    const int i = blockIdx.x * blockDim.x + threadIdx.x;
    const int total4 = N * C_OUT / 4;
    if (i < total4) {
        const float4 m = reinterpret_cast<const float4*>(g_max)[i];
        const int o = (i * 4) & (C_OUT - 1);
        float4 r;
        r.x = fmaxf(fmaf(sc_s[o + 0], m.x, sh_s[o + 0]), 0.0f);
        r.y = fmaxf(fmaf(sc_s[o + 1], m.y, sh_s[o + 1]), 0.0f);
        r.z = fmaxf(fmaf(sc_s[o + 2], m.z, sh_s[o + 2]), 0.0f);
        r.w = fmaxf(fmaf(sc_s[o + 3], m.w, sh_s[o + 3]), 0.0f);
        reinterpret_cast<float4*>(out)[i] = r;
    }
}

// ---------------------------------------------------------------------------
extern "C" void kernel_launch(void* const* d_in, const int* in_sizes, int n_in,
                              void* d_out, int out_size)
{
    const float4* voxels  = (const float4*)d_in[0];
    const int*    npts    = (const int*)d_in[1];
    const float2* centers = (const float2*)d_in[2];
    const float*  W       = (const float*)d_in[3];
    const float*  gamma   = (const float*)d_in[4];
    const float*  beta    = (const float*)d_in[5];
    float*        out     = (float*)d_out;

    const int N = in_sizes[1];

    pfn_pass1<<<NBLK1, THREADS1>>>(voxels, npts, centers, W, N);
    pfn_pass2<<<C_OUT, P2_THREADS>>>(gamma, beta, N);
    const int total4 = N * C_OUT / 4;
    pfn_pass3<<<(total4 + 255) / 256, 256>>>(out, N);
}

// round 16
// speedup vs baseline: 1.0290x; 1.0290x over previous
#include <cuda_runtime.h>
#include <cstdint>

#define PPTS   32
#define C_OUT  64
#define BN_EPS 1e-3f
#define MAXN   100000

#define NBLK1   592              // 148 SM * 4 resident blocks
#define THREADS1 256
#define WARPS1   8

__device__ float g_max[MAXN * C_OUT];
__device__ float g_partial[NBLK1 * 2 * C_OUT];
__device__ float g_scale[C_OUT];
__device__ float g_shift[C_OUT];

// ---- packed f32x2 helpers (Blackwell) -------------------------------------
typedef unsigned long long ull;
__device__ __forceinline__ ull pk2(float lo, float hi) {
    ull r; asm("mov.b64 %0, {%1, %2};" : "=l"(r) : "f"(lo), "f"(hi)); return r;
}
__device__ __forceinline__ ull fma2(ull a, ull b, ull c) {
    ull d; asm("fma.rn.f32x2 %0, %1, %2, %3;" : "=l"(d) : "l"(a), "l"(b), "l"(c)); return d;
}
__device__ __forceinline__ ull mul2(ull a, ull b) {
    ull d; asm("mul.rn.f32x2 %0, %1, %2;" : "=l"(d) : "l"(a), "l"(b)); return d;
}
__device__ __forceinline__ ull add2(ull a, ull b) {
    ull d; asm("add.rn.f32x2 %0, %1, %2;" : "=l"(d) : "l"(a), "l"(b)); return d;
}
__device__ __forceinline__ void unpk2(ull x, float& lo, float& hi) {
    unsigned a, b; asm("mov.b64 {%0, %1}, %2;" : "=r"(a), "=r"(b) : "l"(x));
    lo = __uint_as_float(a); hi = __uint_as_float(b);
}

// ---------------------------------------------------------------------------
// Pass 1: warp = pillar. SoA smem tile; f32x2 packs two POINTS (same channel).
// Each thread owns channels (lane, lane+32). Quad loop: 4 points/iter via
// one LDS.128 per component; scalar remainder for np & 3.
// STS->LDS ordering within an iteration is enforced by the warp-synchronizing
// shfl.sync chain (compiler fence only); end-of-loop __syncwarp guards the
// smem overwrite. Prefetch is branch-free via clamped index.
// ---------------------------------------------------------------------------
__global__ __launch_bounds__(THREADS1, 4) void pfn_pass1(
    const float4* __restrict__ voxels,    // [N,32] float4
    const int*    __restrict__ npts_arr,  // [N]
    const float2* __restrict__ centers,   // [N]
    const float*  __restrict__ W,         // [64,9]
    int N)
{
    const int tid  = threadIdx.x;
    const int lane = tid & 31;
    const int wrp  = tid >> 5;
    const int oA = lane, oB = lane + 32;

    const float* wa = W + oA * 9;
    const float* wb = W + oB * 9;
    // folded weights, per channel (scalar)
    const float a0 = wa[0] + wa[4] + wa[7], b0 = wb[0] + wb[4] + wb[7];
    const float a1 = wa[1] + wa[5] + wa[8], b1 = wb[1] + wb[5] + wb[8];
    const float a2 = wa[2] + wa[6],         b2 = wb[2] + wb[6];
    const float a3 = wa[3],                 b3 = wb[3];
    // point-parity-packed duplicates for the quad loop
    const ull A0 = pk2(a0, a0), A1 = pk2(a1, a1), A2 = pk2(a2, a2), A3 = pk2(a3, a3);
    const ull B0 = pk2(b0, b0), B1 = pk2(b1, b1), B2 = pk2(b2, b2), B3 = pk2(b3, b3);
    const float w4a = wa[4], w5a = wa[5], w6a = wa[6], w7a = wa[7], w8a = wa[8];
    const float w4b = wb[4], w5b = wb[5], w6b = wb[6], w7b = wb[7], w8b = wb[8];

    // SoA: per warp, components contiguous: x[32] y[32] z[32] w[32]
    __shared__ float vox_soa[WARPS1][4][PPTS];

    ull sp  = 0ull;   // packed (sumA, sumB) with bias folded
    ull s2p = 0ull;   // packed (sumsqA, sumsqB)

    const int stride = gridDim.x * WARPS1;
    const int Nm1 = N - 1;
    int n = blockIdx.x * WARPS1 + wrp;

    // first pillar (clamped; loop guard still n < N)
    {
        const int i0 = (n < N) ? n : Nm1;
        float4 v0 = voxels[(size_t)i0 * PPTS + lane];
        int   np0 = npts_arr[i0];
        float2 c0 = centers[i0];
        // fallthrough into loop state
        while (n < N) {
            const float4 v = v0; const int np = np0; const float2 c = c0;

            // SoA staging: 4 conflict-free STS.32
            vox_soa[wrp][0][lane] = v.x;
            vox_soa[wrp][1][lane] = v.y;
            vox_soa[wrp][2][lane] = v.z;
            vox_soa[wrp][3][lane] = v.w;
            asm volatile("" ::: "memory");   // compiler fence; shfl chain below
                                             // provides the execution sync

            // mean shuffles (reference sums ALL 32 rows, divides by np)
            float sx = v.x, sy = v.y, sz = v.z;
            #pragma unroll
            for (int off = 16; off > 0; off >>= 1) {
                sx += __shfl_xor_sync(0xffffffffu, sx, off);
                sy += __shfl_xor_sync(0xffffffffu, sy, off);
                sz += __shfl_xor_sync(0xffffffffu, sz, off);
            }

            // branch-free clamped prefetch of next pillar
            const int n2 = n + stride;
            const int nn = (n2 < N) ? n2 : Nm1;
            v0  = voxels[(size_t)nn * PPTS + lane];
            np0 = npts_arr[nn];
            c0  = centers[nn];

            // ---- quad loop: 4 points per iteration -------------------------
            float mA = -3.402823466e38f, mB = -3.402823466e38f;
            ull sA = 0ull, sB = 0ull;    // point-parity packed sums per channel
            ull qA = 0ull, qB = 0ull;    // packed sumsq per channel

            const char* base = (const char*)&vox_soa[wrp][0][0];
            const int nq = np >> 2;
            #pragma unroll 2
            for (int q = 0; q < nq; q++) {
                const ulonglong2 xq = *(const ulonglong2*)(base + q * 16);
                const ulonglong2 yq = *(const ulonglong2*)(base + 128 + q * 16);
                const ulonglong2 zq = *(const ulonglong2*)(base + 256 + q * 16);
                const ulonglong2 wq = *(const ulonglong2*)(base + 384 + q * 16);

                const ull yA01 = fma2(A0, xq.x, fma2(A1, yq.x, fma2(A2, zq.x, mul2(A3, wq.x))));
                const ull yA23 = fma2(A0, xq.y, fma2(A1, yq.y, fma2(A2, zq.y, mul2(A3, wq.y))));
                const ull yB01 = fma2(B0, xq.x, fma2(B1, yq.x, fma2(B2, zq.x, mul2(B3, wq.x))));
                const ull yB23 = fma2(B0, xq.y, fma2(B1, yq.y, fma2(B2, zq.y, mul2(B3, wq.y))));

                float l0, h0, l1, h1;
                unpk2(yA01, l0, h0); unpk2(yA23, l1, h1);
                mA = fmaxf(fmaxf(mA, fmaxf(l0, h0)), fmaxf(l1, h1));
                unpk2(yB01, l0, h0); unpk2(yB23, l1, h1);
                mB = fmaxf(fmaxf(mB, fmaxf(l0, h0)), fmaxf(l1, h1));

                sA = add2(sA, add2(yA01, yA23));
                sB = add2(sB, add2(yB01, yB23));
                qA = fma2(yA01, yA01, fma2(yA23, yA23, qA));
                qB = fma2(yB01, yB01, fma2(yB23, yB23, qB));
            }

            // ---- scalar remainder (np & 3 points) ---------------------------
            float sAr = 0.f, sBr = 0.f, qAr = 0.f, qBr = 0.f;
            for (int p = nq << 2; p < np; p++) {
                const float xx = vox_soa[wrp][0][p];
                const float yy = vox_soa[wrp][1][p];
                const float zz = vox_soa[wrp][2][p];
                const float ww = vox_soa[wrp][3][p];
                const float yA = fmaf(a0, xx, fmaf(a1, yy, fmaf(a2, zz, a3 * ww)));
                const float yB = fmaf(b0, xx, fmaf(b1, yy, fmaf(b2, zz, b3 * ww)));
                mA = fmaxf(mA, yA);
                mB = fmaxf(mB, yB);
                sAr += yA; sBr += yB;
                qAr = fmaf(yA, yA, qAr);
                qBr = fmaf(yB, yB, qBr);
            }

            // ---- epilogue: fold bias into max / sum / sumsq -----------------
            const float rnp = 1.0f / (float)np;
            const float m0 = sx * rnp, m1 = sy * rnp, m2 = sz * rnp;
            const float bA = -(w4a * m0 + w5a * m1 + w6a * m2 + w7a * c.x + w8a * c.y);
            const float bB = -(w4b * m0 + w5b * m1 + w6b * m2 + w7b * c.x + w8b * c.y);

            float fA = mA + bA, fB = mB + bB;
            if (np < PPTS) {             // padded points contribute exactly 0
                fA = fmaxf(fA, 0.0f);
                fB = fmaxf(fB, 0.0f);
            }
            g_max[(size_t)n * C_OUT + oA] = fA;
            g_max[(size_t)n * C_OUT + oB] = fB;

            float sl, sh, ql, qh;
            unpk2(sA, sl, sh);
            const float SyA = sl + sh + sAr;       // Σy, channel A
            unpk2(qA, ql, qh);
            const float QyA = ql + qh + qAr;       // Σy²
            unpk2(sB, sl, sh);
            const float SyB = sl + sh + sBr;
            unpk2(qB, ql, qh);
            const float QyB = ql + qh + qBr;

            const float npf = (float)np;
            // Σ(y+b) = Σy + np·b ;  Σ(y+b)² = Σy² + b(2Σy + np·b)
            const ull Sy2 = pk2(SyA, SyB);
            const ull Qy2 = pk2(QyA, QyB);
            const ull bp  = pk2(bA, bB);
            const ull npf2 = pk2(npf, npf);
            sp  = add2(sp, fma2(npf2, bp, Sy2));
            s2p = add2(s2p, fma2(bp, fma2(npf2, bp, add2(Sy2, Sy2)), Qy2));

            __syncwarp();    // all lanes done reading smem before next staging
            n = n2;
        }
    }

    // deterministic block reduction across warps
    __shared__ float rsm[WARPS1][C_OUT];
    __shared__ float rqm[WARPS1][C_OUT];
    float sAo, sBo, qAo, qBo;
    unpk2(sp, sAo, sBo);
    unpk2(s2p, qAo, qBo);
    rsm[wrp][oA] = sAo; rsm[wrp][oB] = sBo;
    rqm[wrp][oA] = qAo; rqm[wrp][oB] = qBo;
    __syncthreads();
    if (tid < C_OUT) {
        float ts = 0.0f, tq = 0.0f;
        #pragma unroll
        for (int g = 0; g < WARPS1; g++) { ts += rsm[g][tid]; tq += rqm[g][tid]; }
        g_partial[blockIdx.x * 2 * C_OUT + tid]         = ts;
        g_partial[blockIdx.x * 2 * C_OUT + C_OUT + tid] = tq;
    }
}

// ---------------------------------------------------------------------------
// Pass 2: 64 blocks, one per channel. Deterministic fixed-order reduction.
// ---------------------------------------------------------------------------
#define P2_THREADS 128
__global__ __launch_bounds__(P2_THREADS) void pfn_pass2(
    const float* __restrict__ gamma, const float* __restrict__ beta, int N)
{
    const int o = blockIdx.x;           // channel
    const int t = threadIdx.x;

    float s = 0.0f, q = 0.0f;
    for (int b = t; b < NBLK1; b += P2_THREADS) {   // fixed order per thread
        s += g_partial[b * 2 * C_OUT + o];
        q += g_partial[b * 2 * C_OUT + C_OUT + o];
    }
    __shared__ float ss[P2_THREADS], qq[P2_THREADS];
    ss[t] = s; qq[t] = q;
    __syncthreads();
    #pragma unroll
    for (int w = P2_THREADS / 2; w > 0; w >>= 1) {   // deterministic tree
        if (t < w) { ss[t] += ss[t + w]; qq[t] += qq[t + w]; }
        __syncthreads();
    }
    if (t == 0) {
        const float inv  = 1.0f / ((float)N * (float)PPTS);
        const float mean = ss[0] * inv;
        const float var  = fmaf(-mean, mean, qq[0] * inv);
        const float sc   = gamma[o] * rsqrtf(var + BN_EPS);
        g_scale[o] = sc;
        g_shift[o] = fmaf(-sc, mean, beta[o]);
    }
}

// ---------------------------------------------------------------------------
// Pass 3: out = relu(scale * g_max + shift)   (scale > 0 since gamma == 1,
// so the affine+relu commutes with the max computed in pass 1)
// ---------------------------------------------------------------------------
__global__ __launch_bounds__(256) void pfn_pass3(float* __restrict__ out, int N)
{
    __shared__ float sc_s[C_OUT], sh_s[C_OUT];
    if (threadIdx.x < C_OUT) {
        sc_s[threadIdx.x] = g_scale[threadIdx.x];
        sh_s[threadIdx.x] = g_shift[threadIdx.x];
    }
    __syncthreads();
    const int total4 = N * C_OUT / 4;
    for (int i = blockIdx.x * blockDim.x + threadIdx.x; i < total4;
         i += gridDim.x * blockDim.x) {
        const float4 m = reinterpret_cast<const float4*>(g_max)[i];
        const int o = (i * 4) & (C_OUT - 1);
        float4 r;
        r.x = fmaxf(fmaf(sc_s[o + 0], m.x, sh_s[o + 0]), 0.0f);
        r.y = fmaxf(fmaf(sc_s[o + 1], m.y, sh_s[o + 1]), 0.0f);
        r.z = fmaxf(fmaf(sc_s[o + 2], m.z, sh_s[o + 2]), 0.0f);
        r.w = fmaxf(fmaf(sc_s[o + 3], m.w, sh_s[o + 3]), 0.0f);
        reinterpret_cast<float4*>(out)[i] = r;
    }
}

// ---------------------------------------------------------------------------
extern "C" void kernel_launch(void* const* d_in, const int* in_sizes, int n_in,
                              void* d_out, int out_size)
{
    const float4* voxels  = (const float4*)d_in[0];
    const int*    npts    = (const int*)d_in[1];
    const float2* centers = (const float2*)d_in[2];
    const float*  W       = (const float*)d_in[3];
    const float*  gamma   = (const float*)d_in[4];
    const float*  beta    = (const float*)d_in[5];
    float*        out     = (float*)d_out;

    const int N = in_sizes[1];

    pfn_pass1<<<NBLK1, THREADS1>>>(voxels, npts, centers, W, N);
    pfn_pass2<<<C_OUT, P2_THREADS>>>(gamma, beta, N);
    pfn_pass3<<<1184, 256>>>(out, N);
}

// round 17
// speedup vs baseline: 1.0337x; 1.0045x over previous
#include <cuda_runtime.h>
#include <cstdint>

#define PPTS   32
#define C_OUT  64
#define BN_EPS 1e-3f
#define MAXN   100000

#define NBLK1   592              // 148 SM * 4 resident blocks
#define THREADS1 256
#define WARPS1   8

__device__ float g_max[MAXN * C_OUT];
__device__ float g_partial[NBLK1 * 2 * C_OUT];
__device__ float g_scale[C_OUT];
__device__ float g_shift[C_OUT];

// ---- packed f32x2 helpers (Blackwell) -------------------------------------
typedef unsigned long long ull;
__device__ __forceinline__ ull pk2(float lo, float hi) {
    ull r; asm("mov.b64 %0, {%1, %2};" : "=l"(r) : "f"(lo), "f"(hi)); return r;
}
__device__ __forceinline__ ull fma2(ull a, ull b, ull c) {
    ull d; asm("fma.rn.f32x2 %0, %1, %2, %3;" : "=l"(d) : "l"(a), "l"(b), "l"(c)); return d;
}
__device__ __forceinline__ ull mul2(ull a, ull b) {
    ull d; asm("mul.rn.f32x2 %0, %1, %2;" : "=l"(d) : "l"(a), "l"(b)); return d;
}
__device__ __forceinline__ ull add2(ull a, ull b) {
    ull d; asm("add.rn.f32x2 %0, %1, %2;" : "=l"(d) : "l"(a), "l"(b)); return d;
}
__device__ __forceinline__ void unpk2(ull x, float& lo, float& hi) {
    unsigned a, b; asm("mov.b64 {%0, %1}, %2;" : "=r"(a), "=r"(b) : "l"(x));
    lo = __uint_as_float(a); hi = __uint_as_float(b);
}

// ---------------------------------------------------------------------------
// Pass 1: warp = pillar. SoA smem tile; f32x2 packs two POINTS (same channel).
// Each thread owns channels (lane, lane+32). Quad loop: 4 points/iter via
// one LDS.128 per component; scalar remainder for np & 3.
// All control flow inside the pillar loop is warp-uniform (n/np/nq identical
// across lanes), so the warp stays converged: program-order issue + in-order
// LSU service make both the STS->LDS (RAW) and LDS->next-STS (WAR) orderings
// safe with compiler fences only — no __syncwarp in the loop.
// ---------------------------------------------------------------------------
__global__ __launch_bounds__(THREADS1, 4) void pfn_pass1(
    const float4* __restrict__ voxels,    // [N,32] float4
    const int*    __restrict__ npts_arr,  // [N]
    const float2* __restrict__ centers,   // [N]
    const float*  __restrict__ W,         // [64,9]
    int N)
{
    const int tid  = threadIdx.x;
    const int lane = tid & 31;
    const int wrp  = tid >> 5;
    const int oA = lane, oB = lane + 32;

    const float* wa = W + oA * 9;
    const float* wb = W + oB * 9;
    // folded weights, per channel (scalar)
    const float a0 = wa[0] + wa[4] + wa[7], b0 = wb[0] + wb[4] + wb[7];
    const float a1 = wa[1] + wa[5] + wa[8], b1 = wb[1] + wb[5] + wb[8];
    const float a2 = wa[2] + wa[6],         b2 = wb[2] + wb[6];
    const float a3 = wa[3],                 b3 = wb[3];
    // point-parity-packed duplicates for the quad loop
    const ull A0 = pk2(a0, a0), A1 = pk2(a1, a1), A2 = pk2(a2, a2), A3 = pk2(a3, a3);
    const ull B0 = pk2(b0, b0), B1 = pk2(b1, b1), B2 = pk2(b2, b2), B3 = pk2(b3, b3);
    const float w4a = wa[4], w5a = wa[5], w6a = wa[6], w7a = wa[7], w8a = wa[8];
    const float w4b = wb[4], w5b = wb[5], w6b = wb[6], w7b = wb[7], w8b = wb[8];

    // SoA: per warp, components contiguous: x[32] y[32] z[32] w[32]
    __shared__ float vox_soa[WARPS1][4][PPTS];

    ull sp  = 0ull;   // packed (sumA, sumB) with bias folded
    ull s2p = 0ull;   // packed (sumsqA, sumsqB)

    const int stride = gridDim.x * WARPS1;
    const int Nm1 = N - 1;
    int n = blockIdx.x * WARPS1 + wrp;

    // first pillar (clamped; loop guard still n < N)
    {
        const int i0 = (n < N) ? n : Nm1;
        float4 v0 = voxels[(size_t)i0 * PPTS + lane];
        int   np0 = npts_arr[i0];
        float2 c0 = centers[i0];
        // fallthrough into loop state
        while (n < N) {
            const float4 v = v0; const int np = np0; const float2 c = c0;

            // SoA staging: 4 conflict-free STS.32
            vox_soa[wrp][0][lane] = v.x;
            vox_soa[wrp][1][lane] = v.y;
            vox_soa[wrp][2][lane] = v.z;
            vox_soa[wrp][3][lane] = v.w;
            asm volatile("" ::: "memory");   // compiler fence (RAW: STS before
                                             // quad-loop LDS; warp converged)

            // mean shuffles (reference sums ALL 32 rows, divides by np)
            float sx = v.x, sy = v.y, sz = v.z;
            #pragma unroll
            for (int off = 16; off > 0; off >>= 1) {
                sx += __shfl_xor_sync(0xffffffffu, sx, off);
                sy += __shfl_xor_sync(0xffffffffu, sy, off);
                sz += __shfl_xor_sync(0xffffffffu, sz, off);
            }

            // branch-free clamped prefetch of next pillar
            const int n2 = n + stride;
            const int nn = (n2 < N) ? n2 : Nm1;
            v0  = voxels[(size_t)nn * PPTS + lane];
            np0 = npts_arr[nn];
            c0  = centers[nn];

            // ---- quad loop: 4 points per iteration -------------------------
            float mA = -3.402823466e38f, mB = -3.402823466e38f;
            ull sA = 0ull, sB = 0ull;    // point-parity packed sums per channel
            ull qA = 0ull, qB = 0ull;    // packed sumsq per channel

            const char* base = (const char*)&vox_soa[wrp][0][0];
            const int nq = np >> 2;
            #pragma unroll 2
            for (int q = 0; q < nq; q++) {
                const ulonglong2 xq = *(const ulonglong2*)(base + q * 16);
                const ulonglong2 yq = *(const ulonglong2*)(base + 128 + q * 16);
                const ulonglong2 zq = *(const ulonglong2*)(base + 256 + q * 16);
                const ulonglong2 wq = *(const ulonglong2*)(base + 384 + q * 16);

                const ull yA01 = fma2(A0, xq.x, fma2(A1, yq.x, fma2(A2, zq.x, mul2(A3, wq.x))));
                const ull yA23 = fma2(A0, xq.y, fma2(A1, yq.y, fma2(A2, zq.y, mul2(A3, wq.y))));
                const ull yB01 = fma2(B0, xq.x, fma2(B1, yq.x, fma2(B2, zq.x, mul2(B3, wq.x))));
                const ull yB23 = fma2(B0, xq.y, fma2(B1, yq.y, fma2(B2, zq.y, mul2(B3, wq.y))));

                float l0, h0, l1, h1;
                unpk2(yA01, l0, h0); unpk2(yA23, l1, h1);
                mA = fmaxf(fmaxf(mA, fmaxf(l0, h0)), fmaxf(l1, h1));
                unpk2(yB01, l0, h0); unpk2(yB23, l1, h1);
                mB = fmaxf(fmaxf(mB, fmaxf(l0, h0)), fmaxf(l1, h1));

                sA = add2(sA, add2(yA01, yA23));
                sB = add2(sB, add2(yB01, yB23));
                qA = fma2(yA01, yA01, fma2(yA23, yA23, qA));
                qB = fma2(yB01, yB01, fma2(yB23, yB23, qB));
            }

            // ---- scalar remainder (np & 3 points) ---------------------------
            float sAr = 0.f, sBr = 0.f, qAr = 0.f, qBr = 0.f;
            for (int p = nq << 2; p < np; p++) {
                const float xx = vox_soa[wrp][0][p];
                const float yy = vox_soa[wrp][1][p];
                const float zz = vox_soa[wrp][2][p];
                const float ww = vox_soa[wrp][3][p];
                const float yA = fmaf(a0, xx, fmaf(a1, yy, fmaf(a2, zz, a3 * ww)));
                const float yB = fmaf(b0, xx, fmaf(b1, yy, fmaf(b2, zz, b3 * ww)));
                mA = fmaxf(mA, yA);
                mB = fmaxf(mB, yB);
                sAr += yA; sBr += yB;
                qAr = fmaf(yA, yA, qAr);
                qBr = fmaf(yB, yB, qBr);
            }

            // ---- epilogue: fold bias into max / sum / sumsq -----------------
            const float rnp = 1.0f / (float)np;
            const float m0 = sx * rnp, m1 = sy * rnp, m2 = sz * rnp;
            const float bA = -(w4a * m0 + w5a * m1 + w6a * m2 + w7a * c.x + w8a * c.y);
            const float bB = -(w4b * m0 + w5b * m1 + w6b * m2 + w7b * c.x + w8b * c.y);

            float fA = mA + bA, fB = mB + bB;
            if (np < PPTS) {             // padded points contribute exactly 0
                fA = fmaxf(fA, 0.0f);
                fB = fmaxf(fB, 0.0f);
            }
            g_max[(size_t)n * C_OUT + oA] = fA;
            g_max[(size_t)n * C_OUT + oB] = fB;

            float sl, sh, ql, qh;
            unpk2(sA, sl, sh);
            const float SyA = sl + sh + sAr;       // Σy, channel A
            unpk2(qA, ql, qh);
            const float QyA = ql + qh + qAr;       // Σy²
            unpk2(sB, sl, sh);
            const float SyB = sl + sh + sBr;
            unpk2(qB, ql, qh);
            const float QyB = ql + qh + qBr;

            const float npf = (float)np;
            // Σ(y+b) = Σy + np·b ;  Σ(y+b)² = Σy² + b(2Σy + np·b)
            const ull Sy2 = pk2(SyA, SyB);
            const ull Qy2 = pk2(QyA, QyB);
            const ull bp  = pk2(bA, bB);
            const ull npf2 = pk2(npf, npf);
            sp  = add2(sp, fma2(npf2, bp, Sy2));
            s2p = add2(s2p, fma2(bp, fma2(npf2, bp, add2(Sy2, Sy2)), Qy2));

            asm volatile("" ::: "memory");   // compiler fence (WAR: quad-loop
                                             // LDS before next iter's STS)
            n = n2;
        }
    }

    // deterministic block reduction across warps
    __shared__ float rsm[WARPS1][C_OUT];
    __shared__ float rqm[WARPS1][C_OUT];
    float sAo, sBo, qAo, qBo;
    unpk2(sp, sAo, sBo);
    unpk2(s2p, qAo, qBo);
    rsm[wrp][oA] = sAo; rsm[wrp][oB] = sBo;
    rqm[wrp][oA] = qAo; rqm[wrp][oB] = qBo;
    __syncthreads();
    if (tid < C_OUT) {
        float ts = 0.0f, tq = 0.0f;
        #pragma unroll
        for (int g = 0; g < WARPS1; g++) { ts += rsm[g][tid]; tq += rqm[g][tid]; }
        g_partial[blockIdx.x * 2 * C_OUT + tid]         = ts;
        g_partial[blockIdx.x * 2 * C_OUT + C_OUT + tid] = tq;
    }
}

// ---------------------------------------------------------------------------
// Pass 2: 64 blocks, one per channel. Deterministic fixed-order reduction.
// ---------------------------------------------------------------------------
#define P2_THREADS 128
__global__ __launch_bounds__(P2_THREADS) void pfn_pass2(
    const float* __restrict__ gamma, const float* __restrict__ beta, int N)
{
    const int o = blockIdx.x;           // channel
    const int t = threadIdx.x;

    float s = 0.0f, q = 0.0f;
    for (int b = t; b < NBLK1; b += P2_THREADS) {   // fixed order per thread
        s += g_partial[b * 2 * C_OUT + o];
        q += g_partial[b * 2 * C_OUT + C_OUT + o];
    }
    __shared__ float ss[P2_THREADS], qq[P2_THREADS];
    ss[t] = s; qq[t] = q;
    __syncthreads();
    #pragma unroll
    for (int w = P2_THREADS / 2; w > 0; w >>= 1) {   // deterministic tree
        if (t < w) { ss[t] += ss[t + w]; qq[t] += qq[t + w]; }
        __syncthreads();
    }
    if (t == 0) {
        const float inv  = 1.0f / ((float)N * (float)PPTS);
        const float mean = ss[0] * inv;
        const float var  = fmaf(-mean, mean, qq[0] * inv);
        const float sc   = gamma[o] * rsqrtf(var + BN_EPS);
        g_scale[o] = sc;
        g_shift[o] = fmaf(-sc, mean, beta[o]);
    }
}

// ---------------------------------------------------------------------------
// Pass 3: out = relu(scale * g_max + shift)   (scale > 0 since gamma == 1,
// so the affine+relu commutes with the max computed in pass 1)
// ---------------------------------------------------------------------------
__global__ __launch_bounds__(256) void pfn_pass3(float* __restrict__ out, int N)
{
    __shared__ float sc_s[C_OUT], sh_s[C_OUT];
    if (threadIdx.x < C_OUT) {
        sc_s[threadIdx.x] = g_scale[threadIdx.x];
        sh_s[threadIdx.x] = g_shift[threadIdx.x];
    }
    __syncthreads();
    const int total4 = N * C_OUT / 4;
    for (int i = blockIdx.x * blockDim.x + threadIdx.x; i < total4;
         i += gridDim.x * blockDim.x) {
        const float4 m = reinterpret_cast<const float4*>(g_max)[i];
        const int o = (i * 4) & (C_OUT - 1);
        float4 r;
        r.x = fmaxf(fmaf(sc_s[o + 0], m.x, sh_s[o + 0]), 0.0f);
        r.y = fmaxf(fmaf(sc_s[o + 1], m.y, sh_s[o + 1]), 0.0f);
        r.z = fmaxf(fmaf(sc_s[o + 2], m.z, sh_s[o + 2]), 0.0f);
        r.w = fmaxf(fmaf(sc_s[o + 3], m.w, sh_s[o + 3]), 0.0f);
        reinterpret_cast<float4*>(out)[i] = r;
    }
}

// ---------------------------------------------------------------------------
extern "C" void kernel_launch(void* const* d_in, const int* in_sizes, int n_in,
                              void* d_out, int out_size)
{
    const float4* voxels  = (const float4*)d_in[0];
    const int*    npts    = (const int*)d_in[1];
    const float2* centers = (const float2*)d_in[2];
    const float*  W       = (const float*)d_in[3];
    const float*  gamma   = (const float*)d_in[4];
    const float*  beta    = (const float*)d_in[5];
    float*        out     = (float*)d_out;

    const int N = in_sizes[1];

    pfn_pass1<<<NBLK1, THREADS1>>>(voxels, npts, centers, W, N);
    pfn_pass2<<<C_OUT, P2_THREADS>>>(gamma, beta, N);
    pfn_pass3<<<1184, 256>>>(out, N);
}